// round 13
// baseline (speedup 1.0000x reference)
#include <cuda_runtime.h>

#define T_DIM 4096
#define D_DIM 2048
#define TCH   32
#define NT    (T_DIM / TCH)      /* 128 chunks for k1/prefix */
#define TCHM  64                 /* timesteps per k_main CTA (2 chunks) */
#define NTM   (T_DIM / TCHM)     /* 64 -> 256 CTAs total: single wave */
#define BMAX  8
#define NTHREADS 512
#define D4    (D_DIM / 4)        /* 512 */
#define BT    4                  /* timesteps per batch in k_main */
#define NBM   (TCHM / BT)        /* 16 batches */
#define STG   3                  /* cp.async pipeline stages (batches) */
#define PF    8                  /* prefix prefetch ring depth */

typedef unsigned long long u64;

static __device__ float g_Sx[BMAX * NT * D_DIM];
static __device__ float g_Sq[BMAX * NT * D_DIM];
static __device__ float g_So[BMAX * NT * D_DIM];

__device__ __forceinline__ float tanh_fast(float x) {
    float y;
    asm("tanh.approx.f32 %0, %1;" : "=f"(y) : "f"(x));
    return y;
}

/* ---- packed f32x2 helpers ---- */
__device__ __forceinline__ u64 f2mul(u64 a, u64 b) {
    u64 d; asm("mul.rn.f32x2 %0,%1,%2;" : "=l"(d) : "l"(a), "l"(b)); return d;
}
__device__ __forceinline__ u64 f2add(u64 a, u64 b) {
    u64 d; asm("add.rn.f32x2 %0,%1,%2;" : "=l"(d) : "l"(a), "l"(b)); return d;
}
__device__ __forceinline__ u64 f2fma(u64 a, u64 b, u64 c) {
    u64 d; asm("fma.rn.f32x2 %0,%1,%2,%3;" : "=l"(d) : "l"(a), "l"(b), "l"(c)); return d;
}
__device__ __forceinline__ u64 pk2(float lo, float hi) {
    u64 d; asm("mov.b64 %0,{%1,%2};" : "=l"(d) : "f"(lo), "f"(hi)); return d;
}
__device__ __forceinline__ float2 upk2(u64 v) {
    float2 r; asm("mov.b64 {%0,%1},%2;" : "=f"(r.x), "=f"(r.y) : "l"(v)); return r;
}

#define SGN2 0x8000000080000000ULL
#define ABS2 0x7FFFFFFF7FFFFFFFULL

/* packed gelu on a f32x2 pair */
__device__ __forceinline__ u64 gelu2(u64 v, u64 C1p, u64 C2p, u64 Hp) {
    u64 xsq  = f2mul(v, v);
    u64 poly = f2fma(C2p, xsq, C1p);
    u64 u    = f2mul(v, poly);
    float2 uu = upk2(u);
    u64 th = pk2(tanh_fast(uu.x), tanh_fast(uu.y));
    u64 hx = f2mul(v, Hp);
    return f2fma(hx, th, hx);
}

/* chunk sums, packed math, 3 CTAs/SM for higher read occupancy */
__global__ __launch_bounds__(NTHREADS, 3) void k_chunksums(const float* __restrict__ x) {
    int tc = blockIdx.x, b = blockIdx.y;
    int d4 = threadIdx.x;
    const ulonglong2* xp = reinterpret_cast<const ulonglong2*>(x) +
        ((size_t)b * T_DIM + (size_t)tc * TCH) * D4 + d4;

    const u64 C1p = pk2(0.7978845608028654f, 0.7978845608028654f);
    const u64 C2p = pk2(0.035677408136f, 0.035677408136f);
    const u64 Hp  = pk2(0.5f, 0.5f);

    u64 sxa = 0, sxb = 0, sqa = 0, sqb = 0, soa = 0, sob = 0;

#pragma unroll 8
    for (int i = 0; i < TCH; i++) {
        ulonglong2 v = __ldcs(xp + (size_t)i * D4);
        sxa = f2add(sxa, v.x);        sxb = f2add(sxb, v.y);
        sqa = f2fma(v.x, v.x, sqa);   sqb = f2fma(v.y, v.y, sqb);
        soa = f2add(soa, gelu2(v.x, C1p, C2p, Hp));
        sob = f2add(sob, gelu2(v.y, C1p, C2p, Hp));
    }
    size_t o = ((size_t)(b * NT + tc)) * D4 + d4;
    ulonglong2 t;
    t.x = sxa; t.y = sxb; reinterpret_cast<ulonglong2*>(g_Sx)[o] = t;
    t.x = sqa; t.y = sqb; reinterpret_cast<ulonglong2*>(g_Sq)[o] = t;
    t.x = soa; t.y = sob; reinterpret_cast<ulonglong2*>(g_So)[o] = t;
}

/* one thread per (array, b, d); 8-deep prefetch ring.
   Only EVEN chunk records are written (k_main reads chunk 2*tc only). */
__global__ void k_prefix(int B) {
    int idx = blockIdx.x * blockDim.x + threadIdx.x;
    int bd = B * D_DIM;
    if (idx >= 3 * bd) return;
    int part = idx / bd;
    int rem = idx - part * bd;

    float* arr = (part == 0) ? g_Sx : (part == 1) ? g_Sq : g_So;
    size_t base = (size_t)(rem / D_DIM) * NT * D_DIM + (rem % D_DIM);

    float buf[PF];
#pragma unroll
    for (int k = 0; k < PF; k++)
        buf[k] = arr[base + (size_t)k * D_DIM];

    float r = 0.f;
#pragma unroll 8
    for (int tc = 0; tc < NT; tc++) {
        float cur = buf[tc & (PF - 1)];
        if (tc + PF < NT)
            buf[tc & (PF - 1)] = arr[base + (size_t)(tc + PF) * D_DIM];
        if ((tc & 1) == 0)
            arr[base + (size_t)tc * D_DIM] = r;
        r += cur;
    }
}

/* per-pair compute: 2 elements per packed op */
__device__ __forceinline__ void comp_pair(
    u64 xp, u64& cx, u64& cq, u64& co,
    u64 invc2, u64& sa2, u64& sg22, u64& sgm2, u64& ge_out,
    u64 C1p, u64 C2p, u64 Hp)
{
    u64 mu  = f2mul(cx, invc2);
    u64 sqm = f2mul(cq, invc2);
    u64 nmu = mu ^ SGN2;
    u64 var = f2fma(nmu, mu, sqm);
    float2 v = upk2(var);
    float r0 = rsqrtf(fmaxf(v.x, 1e-4f));
    float r1 = rsqrtf(fmaxf(v.y, 1e-4f));
    float i0 = r0 * fmaf(-1e-5f, r0, 1.0f);
    float i1 = r1 * fmaf(-1e-5f, r1, 1.0f);
    u64 inv2 = pk2(i0, i1);
    u64 diff = f2add(xp, nmu);
    u64 ad   = diff & ABS2;
    sa2 = f2fma(ad, inv2, sa2);
    u64 ge = gelu2(xp, C1p, C2p, Hp);
    sg22 = f2fma(ge, ge, sg22);
    sgm2 = f2fma(ge, co, sgm2);
    cx = f2add(cx, xp);
    cq = f2fma(xp, xp, cq);
    co = f2add(co, ge);
    ge_out = ge;
}

__global__ __launch_bounds__(NTHREADS, 2) void k_main(const float* __restrict__ x,
                                                      float* __restrict__ out,
                                                      const float* __restrict__ p_lt,
                                                      const float* __restrict__ p_ls,
                                                      const float* __restrict__ p_lw) {
    extern __shared__ float4 sbuf[];     /* [STG][BT][D4] = 96 KB */
    __shared__ float4 part[2][BT][17];
    __shared__ float  s2red[16];

    int tc = blockIdx.x, b = blockIdx.y;
    int tid = threadIdx.x;
    int lane = tid & 31, warp = tid >> 5;

    float tau   = __expf(p_lt[0]);
    float sigma = log1pf(__expf(p_ls[0]));
    float w     = log1pf(__expf(p_lw[0]));

    const u64 C1p = pk2(0.7978845608028654f, 0.7978845608028654f);
    const u64 C2p = pk2(0.035677408136f, 0.035677408136f);
    const u64 Hp  = pk2(0.5f, 0.5f);

    /* scratch state at the start of this CTA's first chunk (chunk 2*tc) */
    size_t sidx = ((size_t)(b * NT + tc * (TCHM / TCH))) * D4 + tid;
    ulonglong2 scx = reinterpret_cast<const ulonglong2*>(g_Sx)[sidx];
    ulonglong2 scq = reinterpret_cast<const ulonglong2*>(g_Sq)[sidx];
    ulonglong2 sco = reinterpret_cast<const ulonglong2*>(g_So)[sidx];
    u64 cxa = scx.x, cxb = scx.y;
    u64 cqa = scq.x, cqb = scq.y;
    u64 coa = sco.x, cob = sco.y;

    int t0 = tc * TCHM;
    const float4* xp = reinterpret_cast<const float4*>(x) +
        ((size_t)b * T_DIM + t0) * D4 + tid;
    float4* op = reinterpret_cast<float4*>(out) +
        ((size_t)b * T_DIM + t0) * D4 + tid;

    unsigned sbase = (unsigned)__cvta_generic_to_shared(sbuf);

    /* prologue: fill STG stages */
#pragma unroll
    for (int s = 0; s < STG; s++) {
#pragma unroll
        for (int j = 0; j < BT; j++) {
            const float4* src = xp + (size_t)(s * BT + j) * D4;
            unsigned dst = sbase + (unsigned)(((s * BT + j) * D4 + tid) * 16);
            asm volatile("cp.async.cg.shared.global [%0], [%1], 16;"
                         :: "r"(dst), "l"(src) : "memory");
        }
        asm volatile("cp.async.commit_group;" ::: "memory");
    }

    /* S2 = sum_d co^2 at block start */
    float S2b;
    {
        float2 ca = upk2(coa), cb = upk2(cob);
        float s0 = ca.x * ca.x + ca.y * ca.y + cb.x * cb.x + cb.y * cb.y;
#pragma unroll
        for (int off = 16; off; off >>= 1)
            s0 += __shfl_xor_sync(0xffffffffu, s0, off);
        if (lane == 0) s2red[warp] = s0;
        __syncthreads();
        S2b = 0.f;
#pragma unroll
        for (int ww = 0; ww < 16; ww++) S2b += s2red[ww];
    }

    int stage = 0;
    for (int bt = 0; bt < NBM; bt++) {
        asm volatile("cp.async.wait_group 2;" ::: "memory");

        int ib = bt * BT;
        int pb = bt & 1;
        u64 ga[BT], gb[BT];

#pragma unroll
        for (int j = 0; j < BT; j++) {
            ulonglong2 xin = reinterpret_cast<const ulonglong2*>(sbuf)
                                 [(stage * BT + j) * D4 + tid];
            float invc = __fdividef(1.0f, (float)(t0 + ib + j + 1));
            u64 invc2 = pk2(invc, invc);
            u64 sa2 = 0, sg22 = 0, sgm2 = 0;

            comp_pair(xin.x, cxa, cqa, coa, invc2, sa2, sg22, sgm2, ga[j],
                      C1p, C2p, Hp);
            comp_pair(xin.y, cxb, cqb, cob, invc2, sa2, sg22, sgm2, gb[j],
                      C1p, C2p, Hp);

            float2 A = upk2(sa2), G = upk2(sg22), M = upk2(sgm2);
            float sa = A.x + A.y, sg2v = G.x + G.y, sgmv = M.x + M.y;
#pragma unroll
            for (int off = 16; off; off >>= 1) {
                sa   += __shfl_xor_sync(0xffffffffu, sa,   off);
                sg2v += __shfl_xor_sync(0xffffffffu, sg2v, off);
                sgmv += __shfl_xor_sync(0xffffffffu, sgmv, off);
            }
            if (lane == 0)
                part[pb][j][warp] = make_float4(sa, sg2v, sgmv, 0.f);
        }

        /* reissue into the just-consumed slot (own 16B only) */
        if (bt + STG < NBM) {
#pragma unroll
            for (int j = 0; j < BT; j++) {
                const float4* src = xp + (size_t)((bt + STG) * BT + j) * D4;
                unsigned dst = sbase + (unsigned)(((stage * BT + j) * D4 + tid) * 16);
                asm volatile("cp.async.cg.shared.global [%0], [%1], 16;"
                             :: "r"(dst), "l"(src) : "memory");
            }
        }
        asm volatile("cp.async.commit_group;" ::: "memory");

        __syncthreads();

        /* gates: lanes 0..15 -> (t = lane>>2, stat = lane&3); S2 by recurrence */
        float gate = 0.f;
        {
            int tt = lane >> 2, ss = lane & 3;
            float vv = 0.f;
            if (lane < 16) {
#pragma unroll
                for (int ww = 0; ww < 16; ww++)
                    vv += reinterpret_cast<const float*>(&part[pb][tt][ww])[ss];
            }
            unsigned m = 0xffffffffu;
            float a  = __shfl_sync(m, vv, (lane & ~3) + 0);
            float g2 = __shfl_sync(m, vv, (lane & ~3) + 1);
            float gm = __shfl_sync(m, vv, (lane & ~3) + 2);
            float q = fmaf(2.0f, gm, g2);
            float q0 = __shfl_sync(m, q, 0);
            float q1 = __shfl_sync(m, q, 4);
            float q2 = __shfl_sync(m, q, 8);
            float q3 = __shfl_sync(m, q, 12);
            float m2 = S2b;
            if (tt > 0) m2 += q0;
            if (tt > 1) m2 += q1;
            if (tt > 2) m2 += q2;
            S2b += (q0 + q1) + (q2 + q3);
            if (ss == 0) {
                float mask = (t0 + ib + tt) >= 1 ? 1.0f : 0.0f;
                float mabz = a * (1.0f / D_DIM) * mask;
                float cosv = gm / (fmaxf(sqrtf(g2), 1e-12f) *
                                   fmaxf(sqrtf(m2), 1e-12f)) * mask;
                float surp = tanh_fast(sigma * mabz);
                gate = __expf(-tau * cosv) * (1.0f + w * surp);
            }
        }

#pragma unroll
        for (int j = 0; j < BT; j++) {
            float gj = __shfl_sync(0xffffffffu, gate, j * 4);
            u64 g2p = pk2(gj, gj);
            ulonglong2 ov;
            ov.x = f2mul(ga[j], g2p);
            ov.y = f2mul(gb[j], g2p);
            __stcs(op + (size_t)(ib + j) * D4, *reinterpret_cast<float4*>(&ov));
        }

        stage = (stage + 1 == STG) ? 0 : stage + 1;
    }
}

extern "C" void kernel_launch(void* const* d_in, const int* in_sizes, int n_in,
                              void* d_out, int out_size) {
    const float* x  = (const float*)d_in[0];
    const float* lt = (const float*)d_in[1];
    const float* ls = (const float*)d_in[2];
    const float* lw = (const float*)d_in[3];
    float* out = (float*)d_out;

    int total = in_sizes[0];
    int B = total / (T_DIM * D_DIM);
    if (B < 1) B = 1;
    if (B > BMAX) B = BMAX;

    static int smem_set = 0;
    const int dyn_smem = STG * BT * D4 * (int)sizeof(float4);   /* 96 KB */
    if (!smem_set) {
        cudaFuncSetAttribute(k_main, cudaFuncAttributeMaxDynamicSharedMemorySize,
                             dyn_smem);
        smem_set = 1;
    }

    dim3 grid1(NT, B);
    k_chunksums<<<grid1, NTHREADS>>>(x);

    int n2 = 3 * B * D_DIM;
    k_prefix<<<(n2 + 255) / 256, 256>>>(B);

    dim3 gridm(NTM, B);
    k_main<<<gridm, NTHREADS, dyn_smem>>>(x, out, lt, ls, lw);
}

// round 14
// speedup vs baseline: 1.0203x; 1.0203x over previous
#include <cuda_runtime.h>

#define T_DIM 4096
#define D_DIM 2048
#define TCH   32
#define NT    (T_DIM / TCH)      /* 128 chunk records for prefix */
#define TCHM  64                 /* timesteps per CTA (k1 and k_main) */
#define NTM   (T_DIM / TCHM)     /* 64 -> 256 CTAs: single wave */
#define BMAX  8
#define NTHREADS 512
#define D4    (D_DIM / 4)        /* 512 */
#define BT    4                  /* timesteps per batch in k_main */
#define NBM   (TCHM / BT)        /* 16 batches */
#define STG   3                  /* cp.async pipeline stages (batches) */
#define PF    8                  /* prefix prefetch ring depth */

typedef unsigned long long u64;

static __device__ float g_Sx[BMAX * NT * D_DIM];
static __device__ float g_Sq[BMAX * NT * D_DIM];
static __device__ float g_So[BMAX * NT * D_DIM];

__device__ __forceinline__ float tanh_fast(float x) {
    float y;
    asm("tanh.approx.f32 %0, %1;" : "=f"(y) : "f"(x));
    return y;
}

__device__ __forceinline__ float gelu_f(float x) {
    float x2 = x * x;
    float u = x * fmaf(0.035677408136f, x2, 0.7978845608028654f);
    float hx = 0.5f * x;
    return fmaf(hx, tanh_fast(u), hx);
}

/* ---- packed f32x2 helpers ---- */
__device__ __forceinline__ u64 f2mul(u64 a, u64 b) {
    u64 d; asm("mul.rn.f32x2 %0,%1,%2;" : "=l"(d) : "l"(a), "l"(b)); return d;
}
__device__ __forceinline__ u64 f2add(u64 a, u64 b) {
    u64 d; asm("add.rn.f32x2 %0,%1,%2;" : "=l"(d) : "l"(a), "l"(b)); return d;
}
__device__ __forceinline__ u64 f2fma(u64 a, u64 b, u64 c) {
    u64 d; asm("fma.rn.f32x2 %0,%1,%2,%3;" : "=l"(d) : "l"(a), "l"(b), "l"(c)); return d;
}
__device__ __forceinline__ u64 pk2(float lo, float hi) {
    u64 d; asm("mov.b64 %0,{%1,%2};" : "=l"(d) : "f"(lo), "f"(hi)); return d;
}
__device__ __forceinline__ float2 upk2(u64 v) {
    float2 r; asm("mov.b64 {%0,%1},%2;" : "=f"(r.x), "=f"(r.y) : "l"(v)); return r;
}

#define SGN2 0x8000000080000000ULL
#define ABS2 0x7FFFFFFF7FFFFFFFULL

/* packed gelu on a f32x2 pair */
__device__ __forceinline__ u64 gelu2(u64 v, u64 C1p, u64 C2p, u64 Hp) {
    u64 xsq  = f2mul(v, v);
    u64 poly = f2fma(C2p, xsq, C1p);
    u64 u    = f2mul(v, poly);
    float2 uu = upk2(u);
    u64 th = pk2(tanh_fast(uu.x), tanh_fast(uu.y));
    u64 hx = f2mul(v, Hp);
    return f2fma(hx, th, hx);
}

/* chunk sums: 64 timesteps per CTA, TWO 32-t records -> 256 CTAs, one wave */
__global__ __launch_bounds__(NTHREADS, 2) void k_chunksums(const float* __restrict__ x) {
    int tc = blockIdx.x, b = blockIdx.y;   /* tc in 0..NTM-1 */
    int d4 = threadIdx.x;
    const float4* xp = reinterpret_cast<const float4*>(x) +
        ((size_t)b * T_DIM + (size_t)tc * TCHM) * D4 + d4;

#pragma unroll
    for (int h = 0; h < 2; h++) {
        float4 sx = make_float4(0.f, 0.f, 0.f, 0.f);
        float4 sq = sx, so = sx;

#pragma unroll 8
        for (int i = 0; i < TCH; i++) {
            float4 v = __ldcs(xp + (size_t)(h * TCH + i) * D4);
            sx.x += v.x; sx.y += v.y; sx.z += v.z; sx.w += v.w;
            sq.x = fmaf(v.x, v.x, sq.x); sq.y = fmaf(v.y, v.y, sq.y);
            sq.z = fmaf(v.z, v.z, sq.z); sq.w = fmaf(v.w, v.w, sq.w);
            so.x += gelu_f(v.x); so.y += gelu_f(v.y);
            so.z += gelu_f(v.z); so.w += gelu_f(v.w);
        }
        size_t o = ((size_t)(b * NT + tc * 2 + h)) * D4 + d4;
        reinterpret_cast<float4*>(g_Sx)[o] = sx;
        reinterpret_cast<float4*>(g_Sq)[o] = sq;
        reinterpret_cast<float4*>(g_So)[o] = so;
    }
}

/* one thread per (array, b, d); 8-deep prefetch ring.
   Only EVEN chunk records are written (k_main reads chunk 2*tc only). */
__global__ void k_prefix(int B) {
    int idx = blockIdx.x * blockDim.x + threadIdx.x;
    int bd = B * D_DIM;
    if (idx >= 3 * bd) return;
    int part = idx / bd;
    int rem = idx - part * bd;

    float* arr = (part == 0) ? g_Sx : (part == 1) ? g_Sq : g_So;
    size_t base = (size_t)(rem / D_DIM) * NT * D_DIM + (rem % D_DIM);

    float buf[PF];
#pragma unroll
    for (int k = 0; k < PF; k++)
        buf[k] = arr[base + (size_t)k * D_DIM];

    float r = 0.f;
#pragma unroll 8
    for (int tc = 0; tc < NT; tc++) {
        float cur = buf[tc & (PF - 1)];
        if (tc + PF < NT)
            buf[tc & (PF - 1)] = arr[base + (size_t)(tc + PF) * D_DIM];
        if ((tc & 1) == 0)
            arr[base + (size_t)tc * D_DIM] = r;
        r += cur;
    }
}

/* per-pair compute: 2 elements per packed op */
__device__ __forceinline__ void comp_pair(
    u64 xp, u64& cx, u64& cq, u64& co,
    u64 invc2, u64& sa2, u64& sg22, u64& sgm2, u64& ge_out,
    u64 C1p, u64 C2p, u64 Hp)
{
    u64 mu  = f2mul(cx, invc2);
    u64 sqm = f2mul(cq, invc2);
    u64 nmu = mu ^ SGN2;
    u64 var = f2fma(nmu, mu, sqm);
    float2 v = upk2(var);
    float r0 = rsqrtf(fmaxf(v.x, 1e-4f));
    float r1 = rsqrtf(fmaxf(v.y, 1e-4f));
    float i0 = r0 * fmaf(-1e-5f, r0, 1.0f);
    float i1 = r1 * fmaf(-1e-5f, r1, 1.0f);
    u64 inv2 = pk2(i0, i1);
    u64 diff = f2add(xp, nmu);
    u64 ad   = diff & ABS2;
    sa2 = f2fma(ad, inv2, sa2);
    u64 ge = gelu2(xp, C1p, C2p, Hp);
    sg22 = f2fma(ge, ge, sg22);
    sgm2 = f2fma(ge, co, sgm2);
    cx = f2add(cx, xp);
    cq = f2fma(xp, xp, cq);
    co = f2add(co, ge);
    ge_out = ge;
}

__global__ __launch_bounds__(NTHREADS, 2) void k_main(const float* __restrict__ x,
                                                      float* __restrict__ out,
                                                      const float* __restrict__ p_lt,
                                                      const float* __restrict__ p_ls,
                                                      const float* __restrict__ p_lw) {
    extern __shared__ float4 sbuf[];     /* [STG][BT][D4] = 96 KB */
    __shared__ float4 part[2][BT][17];
    __shared__ float  s2red[16];

    int tc = blockIdx.x, b = blockIdx.y;
    int tid = threadIdx.x;
    int lane = tid & 31, warp = tid >> 5;

    float tau   = __expf(p_lt[0]);
    float sigma = log1pf(__expf(p_ls[0]));
    float w     = log1pf(__expf(p_lw[0]));

    const u64 C1p = pk2(0.7978845608028654f, 0.7978845608028654f);
    const u64 C2p = pk2(0.035677408136f, 0.035677408136f);
    const u64 Hp  = pk2(0.5f, 0.5f);

    /* scratch state at the start of this CTA's first chunk (chunk 2*tc) */
    size_t sidx = ((size_t)(b * NT + tc * 2)) * D4 + tid;
    ulonglong2 scx = reinterpret_cast<const ulonglong2*>(g_Sx)[sidx];
    ulonglong2 scq = reinterpret_cast<const ulonglong2*>(g_Sq)[sidx];
    ulonglong2 sco = reinterpret_cast<const ulonglong2*>(g_So)[sidx];
    u64 cxa = scx.x, cxb = scx.y;
    u64 cqa = scq.x, cqb = scq.y;
    u64 coa = sco.x, cob = sco.y;

    int t0 = tc * TCHM;
    const float4* xp = reinterpret_cast<const float4*>(x) +
        ((size_t)b * T_DIM + t0) * D4 + tid;
    float4* op = reinterpret_cast<float4*>(out) +
        ((size_t)b * T_DIM + t0) * D4 + tid;

    unsigned sbase = (unsigned)__cvta_generic_to_shared(sbuf);

    /* prologue: fill STG stages */
#pragma unroll
    for (int s = 0; s < STG; s++) {
#pragma unroll
        for (int j = 0; j < BT; j++) {
            const float4* src = xp + (size_t)(s * BT + j) * D4;
            unsigned dst = sbase + (unsigned)(((s * BT + j) * D4 + tid) * 16);
            asm volatile("cp.async.cg.shared.global [%0], [%1], 16;"
                         :: "r"(dst), "l"(src) : "memory");
        }
        asm volatile("cp.async.commit_group;" ::: "memory");
    }

    /* S2 = sum_d co^2 at block start */
    float S2b;
    {
        float2 ca = upk2(coa), cb = upk2(cob);
        float s0 = ca.x * ca.x + ca.y * ca.y + cb.x * cb.x + cb.y * cb.y;
#pragma unroll
        for (int off = 16; off; off >>= 1)
            s0 += __shfl_xor_sync(0xffffffffu, s0, off);
        if (lane == 0) s2red[warp] = s0;
        __syncthreads();
        S2b = 0.f;
#pragma unroll
        for (int ww = 0; ww < 16; ww++) S2b += s2red[ww];
    }

    int stage = 0;
    for (int bt = 0; bt < NBM; bt++) {
        asm volatile("cp.async.wait_group 2;" ::: "memory");

        int ib = bt * BT;
        int pb = bt & 1;
        u64 ga[BT], gb[BT];

#pragma unroll
        for (int j = 0; j < BT; j++) {
            ulonglong2 xin = reinterpret_cast<const ulonglong2*>(sbuf)
                                 [(stage * BT + j) * D4 + tid];
            float invc = __fdividef(1.0f, (float)(t0 + ib + j + 1));
            u64 invc2 = pk2(invc, invc);
            u64 sa2 = 0, sg22 = 0, sgm2 = 0;

            comp_pair(xin.x, cxa, cqa, coa, invc2, sa2, sg22, sgm2, ga[j],
                      C1p, C2p, Hp);
            comp_pair(xin.y, cxb, cqb, cob, invc2, sa2, sg22, sgm2, gb[j],
                      C1p, C2p, Hp);

            float2 A = upk2(sa2), G = upk2(sg22), M = upk2(sgm2);
            float sa = A.x + A.y, sg2v = G.x + G.y, sgmv = M.x + M.y;
#pragma unroll
            for (int off = 16; off; off >>= 1) {
                sa   += __shfl_xor_sync(0xffffffffu, sa,   off);
                sg2v += __shfl_xor_sync(0xffffffffu, sg2v, off);
                sgmv += __shfl_xor_sync(0xffffffffu, sgmv, off);
            }
            if (lane == 0)
                part[pb][j][warp] = make_float4(sa, sg2v, sgmv, 0.f);
        }

        /* reissue into the just-consumed slot (own 16B only) */
        if (bt + STG < NBM) {
#pragma unroll
            for (int j = 0; j < BT; j++) {
                const float4* src = xp + (size_t)((bt + STG) * BT + j) * D4;
                unsigned dst = sbase + (unsigned)(((stage * BT + j) * D4 + tid) * 16);
                asm volatile("cp.async.cg.shared.global [%0], [%1], 16;"
                             :: "r"(dst), "l"(src) : "memory");
            }
        }
        asm volatile("cp.async.commit_group;" ::: "memory");

        __syncthreads();

        /* gates: lanes 0..15 -> (t = lane>>2, stat = lane&3); S2 by recurrence */
        float gate = 0.f;
        {
            int tt = lane >> 2, ss = lane & 3;
            float vv = 0.f;
            if (lane < 16) {
#pragma unroll
                for (int ww = 0; ww < 16; ww++)
                    vv += reinterpret_cast<const float*>(&part[pb][tt][ww])[ss];
            }
            unsigned m = 0xffffffffu;
            float a  = __shfl_sync(m, vv, (lane & ~3) + 0);
            float g2 = __shfl_sync(m, vv, (lane & ~3) + 1);
            float gm = __shfl_sync(m, vv, (lane & ~3) + 2);
            float q = fmaf(2.0f, gm, g2);
            float q0 = __shfl_sync(m, q, 0);
            float q1 = __shfl_sync(m, q, 4);
            float q2 = __shfl_sync(m, q, 8);
            float q3 = __shfl_sync(m, q, 12);
            float m2 = S2b;
            if (tt > 0) m2 += q0;
            if (tt > 1) m2 += q1;
            if (tt > 2) m2 += q2;
            S2b += (q0 + q1) + (q2 + q3);
            if (ss == 0) {
                float mask = (t0 + ib + tt) >= 1 ? 1.0f : 0.0f;
                float mabz = a * (1.0f / D_DIM) * mask;
                float cosv = gm / (fmaxf(sqrtf(g2), 1e-12f) *
                                   fmaxf(sqrtf(m2), 1e-12f)) * mask;
                float surp = tanh_fast(sigma * mabz);
                gate = __expf(-tau * cosv) * (1.0f + w * surp);
            }
        }

#pragma unroll
        for (int j = 0; j < BT; j++) {
            float gj = __shfl_sync(0xffffffffu, gate, j * 4);
            u64 g2p = pk2(gj, gj);
            ulonglong2 ov;
            ov.x = f2mul(ga[j], g2p);
            ov.y = f2mul(gb[j], g2p);
            __stcs(op + (size_t)(ib + j) * D4, *reinterpret_cast<float4*>(&ov));
        }

        stage = (stage + 1 == STG) ? 0 : stage + 1;
    }
}

extern "C" void kernel_launch(void* const* d_in, const int* in_sizes, int n_in,
                              void* d_out, int out_size) {
    const float* x  = (const float*)d_in[0];
    const float* lt = (const float*)d_in[1];
    const float* ls = (const float*)d_in[2];
    const float* lw = (const float*)d_in[3];
    float* out = (float*)d_out;

    int total = in_sizes[0];
    int B = total / (T_DIM * D_DIM);
    if (B < 1) B = 1;
    if (B > BMAX) B = BMAX;

    static int smem_set = 0;
    const int dyn_smem = STG * BT * D4 * (int)sizeof(float4);   /* 96 KB */
    if (!smem_set) {
        cudaFuncSetAttribute(k_main, cudaFuncAttributeMaxDynamicSharedMemorySize,
                             dyn_smem);
        smem_set = 1;
    }

    dim3 grid1(NTM, B);
    k_chunksums<<<grid1, NTHREADS>>>(x);

    int n2 = 3 * B * D_DIM;
    k_prefix<<<(n2 + 255) / 256, 256>>>(B);

    dim3 gridm(NTM, B);
    k_main<<<gridm, NTHREADS, dyn_smem>>>(x, out, lt, ls, lw);
}